// round 9
// baseline (speedup 1.0000x reference)
#include <cuda_runtime.h>
#include <cstdint>
#include <cstddef>

#define CIN   2112
#define COUT  192
#define NB    256
#define HW    49
#define G     2            // batches per block
#define KT    32           // K per k-tile (4 k8 steps)
#define NITER (CIN / KT)   // 66
#define THREADS 512
#define NMT   12           // m16 tiles (192/16)
#define BROWS (G * KT)     // 64 rows in Bs
#define BSTRIDE 72         // Bs row stride in floats (72 mod 32 = 8 -> conflict-free)
#define AS_TILE (NMT * 4 * 32 * 4)   // 6144 floats per W k-tile (fragment-major)
#define BS_TILE (BROWS * BSTRIDE)    // 4608 floats
#define SMEM_BYTES ((2 * AS_TILE + 2 * BS_TILE) * 4)  // 86016

// Scratch (alloc-free rules): BN affine + fragment-major tf32-rounded W
__device__ float g_scale[CIN];
__device__ float g_shift[CIN];
__device__ __align__(16) float g_Wp[COUT * CIN];

__device__ __forceinline__ uint32_t f2tf32(float f) {
    uint32_t t;
    asm("cvt.rna.tf32.f32 %0, %1;" : "=r"(t) : "f"(f));
    return t;
}

// Permute W into fragment-major order:
// g_Wp[((kt*NMT + mt)*4 + kb4)*128 + lane*4 + {0..3}] =
//   tf32(W[row, col]) for the m16n8k8 A-fragment of thread `lane`:
//   a0=(gr,ct) a1=(gr+8,ct) a2=(gr,ct+4) a3=(gr+8,ct+4), row base mt*16, col base (kt*4+kb4)*8
__global__ void prep_kernel(const float* __restrict__ gamma,
                            const float* __restrict__ beta,
                            const float* __restrict__ rmean,
                            const float* __restrict__ rvar,
                            const float* __restrict__ W) {
    int tid = blockIdx.x * blockDim.x + threadIdx.x;
    if (tid < CIN) {
        float inv = rsqrtf(rvar[tid] + 1e-5f);
        float sc  = gamma[tid] * inv;
        g_scale[tid] = sc;
        g_shift[tid] = beta[tid] - rmean[tid] * sc;
    }
    const int total = (COUT * CIN) / 4;   // lane-slots of 4 floats
    for (int s = tid; s < total; s += gridDim.x * blockDim.x) {
        int lane = s & 31;
        int t    = s >> 5;          // (kt*NMT + mt)*4 + kb4
        int kb4  = t & 3;
        int mtt  = t >> 2;
        int mt   = mtt % NMT;
        int kt   = mtt / NMT;
        int gr   = lane >> 2;
        int ct   = lane & 3;
        int k    = kt * KT + kb4 * 8 + ct;
        int r0   = mt * 16 + gr;
        float* dst = g_Wp + (size_t)s * 4;
        dst[0] = __uint_as_float(f2tf32(W[(size_t)r0       * CIN + k]));
        dst[1] = __uint_as_float(f2tf32(W[(size_t)(r0 + 8) * CIN + k]));
        dst[2] = __uint_as_float(f2tf32(W[(size_t)r0       * CIN + k + 4]));
        dst[3] = __uint_as_float(f2tf32(W[(size_t)(r0 + 8) * CIN + k + 4]));
    }
}

__device__ __forceinline__ void cp_async16(uint32_t dst_smem, const void* src) {
    asm volatile("cp.async.cg.shared.global [%0], [%1], 16;\n" :: "r"(dst_smem), "l"(src));
}

__device__ __forceinline__ void mma_tf32(float* d, const uint32_t* a, uint32_t b0, uint32_t b1) {
    asm volatile(
        "mma.sync.aligned.m16n8k8.row.col.f32.tf32.tf32.f32 "
        "{%0,%1,%2,%3}, {%4,%5,%6,%7}, {%8,%9}, {%0,%1,%2,%3};\n"
        : "+f"(d[0]), "+f"(d[1]), "+f"(d[2]), "+f"(d[3])
        : "r"(a[0]), "r"(a[1]), "r"(a[2]), "r"(a[3]), "r"(b0), "r"(b1));
}

__global__ __launch_bounds__(THREADS, 1)
void gemm_kernel(const float* __restrict__ x, float* __restrict__ out) {
    extern __shared__ __align__(16) float smem[];
    float* Asm = smem;                    // 2 * AS_TILE  (fragment-major W tiles)
    float* Bsm = smem + 2 * AS_TILE;      // 2 * BS_TILE  (h tiles, tf32 bits)

    const int tid  = threadIdx.x;
    const int lane = tid & 31;
    const int w    = tid >> 5;
    const int gr   = lane >> 2;
    const int ct   = lane & 3;
    const int wg   = w & 1;          // batch within block
    const int wm   = (w >> 1) & 3;   // m-quarter (3 m16-tiles)
    const int wn   = w >> 3;         // n-half: j in {0..3} or {4..7}
    const int jlo  = wn * 4;
    const int batch0 = blockIdx.x * G;

    float acc[3][4][4];
    #pragma unroll
    for (int i = 0; i < 3; i++)
        #pragma unroll
        for (int j = 0; j < 4; j++)
            #pragma unroll
            for (int q = 0; q < 4; q++) acc[i][j][q] = 0.0f;

    float xr[8];

    // x-load geometry: idx = tid + i*512 in [0, 4096); row = idx>>6 (g*32+kr), col = idx&63
    auto loadX = [&](int kt) {
        #pragma unroll
        for (int i = 0; i < 8; i++) {
            int idx = tid + i * THREADS;
            int row = idx >> 6;
            int col = idx & 63;
            int g   = row >> 5;
            int kr  = row & 31;
            bool ok = (col < HW);
            const float* p = x + ((size_t)(batch0 + g) * CIN + kt * KT + kr) * HW + col;
            xr[i] = ok ? __ldg(p) : 0.0f;
        }
    };
    auto stsB = [&](int p, int kt) {
        float* bdst = Bsm + p * BS_TILE;
        #pragma unroll
        for (int i = 0; i < 8; i++) {
            int idx = tid + i * THREADS;
            int row = idx >> 6;
            int col = idx & 63;
            int kr  = row & 31;
            uint32_t t = 0u;
            if (col < HW) {
                int c = kt * KT + kr;
                float h = fmaxf(fmaf(xr[i], __ldg(g_scale + c), __ldg(g_shift + c)), 0.0f);
                t = f2tf32(h);
            }
            bdst[row * BSTRIDE + col] = __uint_as_float(t);
        }
    };
    auto fillAs = [&](int p, int kt) {
        const float* src = g_Wp + (size_t)kt * AS_TILE;
        float* dst = Asm + p * AS_TILE;
        #pragma unroll
        for (int i = 0; i < 3; i++) {
            int o = tid + i * THREADS;   // float4 index, 0..1535
            uint32_t d = (uint32_t)__cvta_generic_to_shared(dst + o * 4);
            cp_async16(d, src + (size_t)o * 4);
        }
    };
    auto computeTile = [&](int p) {
        const uint4* asp = (const uint4*)(Asm + p * AS_TILE);
        const float* bsp = Bsm + p * BS_TILE + wg * (KT * BSTRIDE);
        #pragma unroll
        for (int kk = 0; kk < 4; kk++) {
            uint4 a[3];
            #pragma unroll
            for (int i = 0; i < 3; i++) {
                int mt = wm * 3 + i;
                a[i] = asp[(mt * 4 + kk) * 32 + lane];
            }
            #pragma unroll
            for (int jj = 0; jj < 4; jj++) {
                int j = jlo + jj;
                uint32_t b0 = __float_as_uint(bsp[(kk * 8 + ct)     * BSTRIDE + j * 8 + gr]);
                uint32_t b1 = __float_as_uint(bsp[(kk * 8 + ct + 4) * BSTRIDE + j * 8 + gr]);
                #pragma unroll
                for (int i = 0; i < 3; i++)
                    mma_tf32(acc[i][jj], (const uint32_t*)&a[i], b0, b1);
            }
        }
    };

    // ---- pipelined main loop ----
    fillAs(0, 0);
    asm volatile("cp.async.commit_group;\n");
    loadX(0);

    for (int kt = 0; kt < NITER; kt++) {
        const int p = kt & 1;
        stsB(p, kt);
        if (kt + 1 < NITER) {
            fillAs(p ^ 1, kt + 1);
            asm volatile("cp.async.commit_group;\n");
            asm volatile("cp.async.wait_group 1;\n");
        } else {
            asm volatile("cp.async.wait_group 0;\n");
        }
        __syncthreads();
        if (kt + 1 < NITER) loadX(kt + 1);
        computeTile(p);
        __syncthreads();
    }

    // ---- epilogue ----
    const int batch = batch0 + wg;
    float* ob = out + (size_t)batch * COUT * HW;
    #pragma unroll
    for (int i = 0; i < 3; i++) {
        const int m  = (wm * 3 + i) * 16;
        const int r0 = m + gr, r1 = m + gr + 8;
        #pragma unroll
        for (int jj = 0; jj < 4; jj++) {
            const int n0 = (jlo + jj) * 8 + 2 * ct;
            if (n0 < HW) {
                ob[r0 * HW + n0] = acc[i][jj][0];
                ob[r1 * HW + n0] = acc[i][jj][2];
            }
            if (n0 + 1 < HW) {
                ob[r0 * HW + n0 + 1] = acc[i][jj][1];
                ob[r1 * HW + n0 + 1] = acc[i][jj][3];
            }
        }
    }
}

extern "C" void kernel_launch(void* const* d_in, const int* in_sizes, int n_in,
                              void* d_out, int out_size) {
    const float* x     = (const float*)d_in[0];
    const float* gamma = (const float*)d_in[1];
    const float* beta  = (const float*)d_in[2];
    const float* rmean = (const float*)d_in[3];
    const float* rvar  = (const float*)d_in[4];
    const float* W     = (const float*)d_in[5];
    float* out = (float*)d_out;

    prep_kernel<<<132, 512>>>(gamma, beta, rmean, rvar, W);

    cudaFuncSetAttribute(gemm_kernel, cudaFuncAttributeMaxDynamicSharedMemorySize, SMEM_BYTES);
    gemm_kernel<<<NB / G, THREADS, SMEM_BYTES>>>(x, out);
}

// round 12
// speedup vs baseline: 1.4913x; 1.4913x over previous
#include <cuda_runtime.h>
#include <cstdint>
#include <cstddef>

#define CIN   2112
#define COUT  192
#define NB    256
#define HW    49
#define G     2                 // batches per CTA
#define KT    16                // K per stage (2 k8 steps)
#define NITER (CIN / KT)        // 132
#define PIPE  4
#define THREADS 512
#define NMT   12                // m16 tiles
#define BSTRIDE 72              // Bs row stride (floats): banks 8ct+8j+gr -> conflict-free
#define AS_T  (NMT * 2 * 32 * 4)     // 3072 floats per W stage (fragment-major)
#define BS_T  (G * KT * BSTRIDE)     // 2304 floats per h stage
#define SMEM_BYTES (PIPE * (AS_T + BS_T) * 4)   // 86016

// device scratch (alloc-free rules)
__device__ float g_scale[CIN];
__device__ float g_shift[CIN];
__device__ __align__(16) float g_Wp[COUT * CIN];   // fragment-major tf32-rounded W

__device__ __forceinline__ uint32_t f2tf32(float f) {
    uint32_t t; asm("cvt.rna.tf32.f32 %0, %1;" : "=r"(t) : "f"(f)); return t;
}

// g_Wp slot s (of 4 floats): lane=s&31; t=s>>5; kk=t&1; mt=(t>>1)%12; kt=(t>>1)/12
// holds A-fragment {a0,a1,a2,a3} of m16n8k8 tile (mt, k=kt*16+kk*8)
__global__ void prep_kernel(const float* __restrict__ gamma,
                            const float* __restrict__ beta,
                            const float* __restrict__ rmean,
                            const float* __restrict__ rvar,
                            const float* __restrict__ W) {
    int tid = blockIdx.x * blockDim.x + threadIdx.x;
    if (tid < CIN) {
        float inv = rsqrtf(rvar[tid] + 1e-5f);
        float sc  = gamma[tid] * inv;
        g_scale[tid] = sc;
        g_shift[tid] = beta[tid] - rmean[tid] * sc;
    }
    const int total = (COUT * CIN) / 4;
    for (int s = tid; s < total; s += gridDim.x * blockDim.x) {
        int lane = s & 31;
        int t    = s >> 5;
        int kk   = t & 1;
        int mtt  = t >> 1;
        int mt   = mtt % NMT;
        int kt   = mtt / NMT;
        int gr   = lane >> 2;
        int ct   = lane & 3;
        int k    = kt * KT + kk * 8 + ct;
        int r0   = mt * 16 + gr;
        float* dst = g_Wp + (size_t)s * 4;
        dst[0] = __uint_as_float(f2tf32(W[(size_t)r0       * CIN + k]));
        dst[1] = __uint_as_float(f2tf32(W[(size_t)(r0 + 8) * CIN + k]));
        dst[2] = __uint_as_float(f2tf32(W[(size_t)r0       * CIN + k + 4]));
        dst[3] = __uint_as_float(f2tf32(W[(size_t)(r0 + 8) * CIN + k + 4]));
    }
}

__device__ __forceinline__ void cp_async16(uint32_t dst, const void* src) {
    asm volatile("cp.async.cg.shared.global [%0], [%1], 16;" :: "r"(dst), "l"(src));
}
__device__ __forceinline__ void mma_tf32(float* d, const uint32_t* a, uint32_t b0, uint32_t b1) {
    asm volatile(
        "mma.sync.aligned.m16n8k8.row.col.f32.tf32.tf32.f32 "
        "{%0,%1,%2,%3}, {%4,%5,%6,%7}, {%8,%9}, {%0,%1,%2,%3};\n"
        : "+f"(d[0]), "+f"(d[1]), "+f"(d[2]), "+f"(d[3])
        : "r"(a[0]), "r"(a[1]), "r"(a[2]), "r"(a[3]), "r"(b0), "r"(b1));
}

template<int JCNT>
__device__ __forceinline__ void computeTile(const uint4* __restrict__ asp,
                                            const float* __restrict__ bsp,
                                            int lane, int gr, int ct, int wm, int jlo,
                                            float acc[3][4][4]) {
    #pragma unroll
    for (int kk = 0; kk < 2; kk++) {
        uint4 a[3];
        #pragma unroll
        for (int i = 0; i < 3; i++) {
            int mt = wm * 3 + i;
            a[i] = asp[(mt * 2 + kk) * 32 + lane];
        }
        #pragma unroll
        for (int jj = 0; jj < JCNT; jj++) {
            int j = jlo + jj;
            uint32_t b0 = __float_as_uint(bsp[(kk * 8 + ct)     * BSTRIDE + j * 8 + gr]);
            uint32_t b1 = __float_as_uint(bsp[(kk * 8 + ct + 4) * BSTRIDE + j * 8 + gr]);
            #pragma unroll
            for (int i = 0; i < 3; i++)
                mma_tf32(acc[i][jj], (const uint32_t*)&a[i], b0, b1);
        }
    }
}

__global__ __launch_bounds__(THREADS, 1)
void gemm_kernel(const float* __restrict__ x, float* __restrict__ out) {
    extern __shared__ __align__(16) float smem[];
    float* Asm = smem;                     // PIPE * AS_T
    float* Bsm = smem + PIPE * AS_T;       // PIPE * BS_T

    const int tid  = threadIdx.x;
    const int lane = tid & 31;
    const int w    = tid >> 5;
    const int gr   = lane >> 2;
    const int ct   = lane & 3;
    const int wg   = w >> 3;          // batch
    const int wr   = w & 7;
    const int wm   = wr >> 1;         // m-group (3 m16 tiles)
    const int wn   = wr & 1;          // n-group: 4 or 3 n8 tiles
    const int jlo  = wn * 4;
    const int batch0 = blockIdx.x * G;

    // per-thread x/B geometry: idx = tid + i*512 in [0,2048): row=idx>>6 (b*16+kr), col=idx&63
    bool ld_ok[4]; int ld_sidx[4], ld_kr[4];
    const float* ld_base[4];
    #pragma unroll
    for (int i = 0; i < 4; i++) {
        int idx = tid + i * THREADS;
        int row = idx >> 6;
        int col = idx & 63;
        int b   = row >> 4;
        int kr  = row & 15;
        ld_ok[i]   = (col < HW);
        ld_kr[i]   = kr;
        ld_sidx[i] = row * BSTRIDE + col;
        ld_base[i] = x + ((size_t)(batch0 + b) * CIN + kr) * HW + col;
    }

    float acc[3][4][4];
    #pragma unroll
    for (int i = 0; i < 3; i++)
        #pragma unroll
        for (int j = 0; j < 4; j++)
            #pragma unroll
            for (int q = 0; q < 4; q++) acc[i][j][q] = 0.0f;

    float xr[4], xr2[4];

    auto loadX = [&](int stage, float* dst) {
        const int off = stage * KT * HW;
        #pragma unroll
        for (int i = 0; i < 4; i++)
            dst[i] = ld_ok[i] ? __ldg(ld_base[i] + off) : 0.0f;
    };
    auto stsB = [&](int stage) {
        float* bdst = Bsm + (stage & 3) * BS_T;
        const int k0 = stage * KT;
        #pragma unroll
        for (int i = 0; i < 4; i++) {
            uint32_t t = 0u;
            if (ld_ok[i]) {
                int c = k0 + ld_kr[i];
                float h = fmaxf(fmaf(xr[i], __ldg(g_scale + c), __ldg(g_shift + c)), 0.0f);
                t = f2tf32(h);
            }
            bdst[ld_sidx[i]] = __uint_as_float(t);
        }
    };
    auto fillAs = [&](int stage) {   // cp.async W stage + commit (one group)
        const float* src = g_Wp + (size_t)stage * AS_T;
        float* dst = Asm + (stage & 3) * AS_T;
        {
            int o = tid;
            cp_async16((uint32_t)__cvta_generic_to_shared(dst + o * 4), src + (size_t)o * 4);
        }
        if (tid < AS_T / 4 - THREADS) {
            int o = THREADS + tid;
            cp_async16((uint32_t)__cvta_generic_to_shared(dst + o * 4), src + (size_t)o * 4);
        }
        asm volatile("cp.async.commit_group;");
    };

    // ---- prologue: stages 0..2 in smem, stage 3 data in regs ----
    #pragma unroll
    for (int ps = 0; ps < 3; ps++) {
        loadX(ps, xr);
        stsB(ps);
        fillAs(ps);
    }
    loadX(3, xr);

    // ---- main loop: one sync per stage ----
    for (int s = 0; s < NITER; s++) {
        if (s < NITER - 2)       asm volatile("cp.async.wait_group 2;");
        else if (s == NITER - 2) asm volatile("cp.async.wait_group 1;");
        else                     asm volatile("cp.async.wait_group 0;");
        __syncthreads();

        if (s + 3 < NITER) fillAs(s + 3);
        if (s + 4 < NITER) loadX(s + 4, xr2);
        if (s + 3 < NITER) stsB(s + 3);

        const uint4*  asp = (const uint4*)(Asm + (s & 3) * AS_T);
        const float*  bsp = Bsm + (s & 3) * BS_T + wg * (KT * BSTRIDE);
        if (wn == 0) computeTile<4>(asp, bsp, lane, gr, ct, wm, jlo, acc);
        else         computeTile<3>(asp, bsp, lane, gr, ct, wm, jlo, acc);

        #pragma unroll
        for (int i = 0; i < 4; i++) xr[i] = xr2[i];
    }

    // ---- epilogue ----
    const int jcnt = wn ? 3 : 4;
    float* ob = out + (size_t)(batch0 + wg) * COUT * HW;
    #pragma unroll
    for (int i = 0; i < 3; i++) {
        const int m  = (wm * 3 + i) * 16;
        const int r0 = m + gr, r1 = m + gr + 8;
        #pragma unroll
        for (int jj = 0; jj < 4; jj++) {
            if (jj >= jcnt) break;
            const int n0 = (jlo + jj) * 8 + 2 * ct;
            if (n0 < HW) {
                ob[r0 * HW + n0] = acc[i][jj][0];
                ob[r1 * HW + n0] = acc[i][jj][2];
            }
            if (n0 + 1 < HW) {
                ob[r0 * HW + n0 + 1] = acc[i][jj][1];
                ob[r1 * HW + n0 + 1] = acc[i][jj][3];
            }
        }
    }
}

extern "C" void kernel_launch(void* const* d_in, const int* in_sizes, int n_in,
                              void* d_out, int out_size) {
    const float* x     = (const float*)d_in[0];
    const float* gamma = (const float*)d_in[1];
    const float* beta  = (const float*)d_in[2];
    const float* rmean = (const float*)d_in[3];
    const float* rvar  = (const float*)d_in[4];
    const float* W     = (const float*)d_in[5];
    float* out = (float*)d_out;

    prep_kernel<<<132, 512>>>(gamma, beta, rmean, rvar, W);

    cudaFuncSetAttribute(gemm_kernel, cudaFuncAttributeMaxDynamicSharedMemorySize, SMEM_BYTES);
    gemm_kernel<<<NB / G, THREADS, SMEM_BYTES>>>(x, out);
}